// round 16
// baseline (speedup 1.0000x reference)
#include <cuda_runtime.h>
#include <cuda_fp16.h>
#include <cstdint>
#include <math.h>

#define D_MODEL 2048
#define SEQ     2048
#define N_HEADS 16
#define HEAD_DIM 128

__device__ __half g_Q[SEQ * D_MODEL];
__device__ __half g_K[SEQ * D_MODEL];
__device__ __half g_Vt[D_MODEL * SEQ];
__device__ __half g_A[SEQ * D_MODEL];
__device__ __half g_X[SEQ * D_MODEL];
__device__ __half g_WT4[4 * D_MODEL * D_MODEL];

// ---------------------------------------------------------------------------
static __device__ __forceinline__ uint32_t smem_u32(const void* p) {
    return (uint32_t)__cvta_generic_to_shared(p);
}

#define LDSM_X4(r0, r1, r2, r3, addr) \
    asm volatile("ldmatrix.sync.aligned.m8n8.x4.shared.b16 {%0,%1,%2,%3}, [%4];" \
                 : "=r"(r0), "=r"(r1), "=r"(r2), "=r"(r3) : "r"(addr))

static __device__ __forceinline__ void mma_f16(
    float* c, const uint32_t* a, uint32_t b0, uint32_t b1)
{
    asm volatile(
        "mma.sync.aligned.m16n8k16.row.col.f32.f16.f16.f32 "
        "{%0,%1,%2,%3}, {%4,%5,%6,%7}, {%8,%9}, {%0,%1,%2,%3};"
        : "+f"(c[0]), "+f"(c[1]), "+f"(c[2]), "+f"(c[3])
        : "r"(a[0]), "r"(a[1]), "r"(a[2]), "r"(a[3]), "r"(b0), "r"(b1));
}

static __device__ __forceinline__ uint32_t pack_half2(float lo, float hi) {
    uint32_t r;
    asm("cvt.rn.f16x2.f32 %0, %1, %2;" : "=r"(r) : "f"(hi), "f"(lo));
    return r;
}

static __device__ __forceinline__ uint32_t ex2_f16x2(uint32_t a) {
    uint32_t r;
    asm("ex2.approx.f16x2 %0, %1;" : "=r"(r) : "r"(a));
    return r;
}

static __device__ __forceinline__ float ex2_f32(float x) {
    float r;
    asm("ex2.approx.f32 %0, %1;" : "=f"(r) : "f"(x));
    return r;
}

static __device__ __forceinline__ void cp_async16(uint32_t dst, const void* src) {
    asm volatile("cp.async.cg.shared.global [%0], [%1], 16;"
                 :: "r"(dst), "l"(src) : "memory");
}
#define CP_COMMIT() asm volatile("cp.async.commit_group;" ::: "memory")
#define CP_WAIT(n)  asm volatile("cp.async.wait_group %0;" :: "n"(n) : "memory")

// ---------------------------------------------------------------------------
// prep: z=0 convert x->fp16 ; z=1..4 transpose+convert wq/wk/wv/wo
// ---------------------------------------------------------------------------
__global__ __launch_bounds__(256) void prep_kernel(
    const float* __restrict__ x,
    const float* __restrict__ wq, const float* __restrict__ wk,
    const float* __restrict__ wv, const float* __restrict__ wo,
    __half* __restrict__ X, __half* __restrict__ WT)
{
    const size_t WSZ = (size_t)D_MODEL * D_MODEL;
    int z = blockIdx.z;
    if (z == 0) {
        int c = blockIdx.x * 32 + threadIdx.x;
#pragma unroll
        for (int i = 0; i < 4; i++) {
            int r = blockIdx.y * 32 + threadIdx.y + i * 8;
            X[(size_t)r * D_MODEL + c] = __float2half_rn(x[(size_t)r * D_MODEL + c]);
        }
        return;
    }
    const float* in = (z == 1) ? wq : (z == 2) ? wk : (z == 3) ? wv : wo;
    __half* out = WT + (size_t)(z - 1) * WSZ;

    __shared__ float tile[32][33];
    int xx = blockIdx.x * 32 + threadIdx.x;
    int yy = blockIdx.y * 32 + threadIdx.y;
#pragma unroll
    for (int i = 0; i < 32; i += 8)
        tile[threadIdx.y + i][threadIdx.x] = in[(size_t)(yy + i) * D_MODEL + xx];
    __syncthreads();
    xx = blockIdx.y * 32 + threadIdx.x;
    yy = blockIdx.x * 32 + threadIdx.y;
#pragma unroll
    for (int i = 0; i < 32; i += 8)
        out[(size_t)(yy + i) * D_MODEL + xx] = __float2half_rn(tile[threadIdx.x][threadIdx.y + i]);
}

// ---------------------------------------------------------------------------
// fp16 mma.sync GEMM v3: CTA 128x256, 512 threads / 16 warps, warp 32x64,
// BK=128 (256B rows), 2-stage cp.async (A 32K + B 64K per stage = 192K).
// Half the barrier count of BK=64/4-stage; same swizzle family.
// ---------------------------------------------------------------------------
#define GSTAGE_BYTES 98304
#define GEMM_SMEM_BYTES (2 * GSTAGE_BYTES)

__global__ __launch_bounds__(512, 1) void gemm_tc_kernel(
    const __half* __restrict__ A, const __half* __restrict__ BT,
    __half* __restrict__ C0, __half* __restrict__ C1, __half* __restrict__ C2,
    float* __restrict__ Cf,
    const float* __restrict__ fc, const float* __restrict__ fs,
    int tiles_per_mat, int rope_mats, int vt_mat)
{
    extern __shared__ char smc[];
    uint32_t sb = smem_u32(smc);

    int t    = threadIdx.x;
    int lane = t & 31;
    int wid  = t >> 5;
    int row0 = blockIdx.y << 7;
    int bx   = blockIdx.x;
    int mat  = bx / tiles_per_mat;
    int col0 = (bx % tiles_per_mat) << 8;
    __half* C = (mat == 0) ? C0 : (mat == 1 ? C1 : C2);
    const __half* Arow = A + (size_t)row0 * D_MODEL;
    const __half* Brow = BT + ((size_t)bx << 8) * D_MODEL;
    bool dorope = (mat < rope_mats);
    bool dovt   = (mat == vt_mat);

    int wm = (wid >> 2) << 5;
    int wn = (wid & 3) << 6;

    float acc[2][8][4];
#pragma unroll
    for (int i = 0; i < 2; i++)
#pragma unroll
        for (int j = 0; j < 8; j++)
#pragma unroll
            for (int q = 0; q < 4; q++) acc[i][j][q] = 0.0f;

    uint32_t arow  = (uint32_t)(wm + (lane & 15));
    uint32_t acsel = (uint32_t)((lane >> 4) & 1);
    uint32_t brow  = (uint32_t)(wn + (lane & 7) + ((lane >> 4) & 1) * 8);
    uint32_t bcsel = (uint32_t)((lane >> 3) & 1);
    uint32_t asw7  = arow & 7;
    uint32_t bsw7  = brow & 7;

    // copy geometry (BK=128 halfs = 16 x 16B chunks per 256B row)
    const int ar  = t >> 2;            // A row 0..127
    const int ac0 = (t & 3) << 2;      // A chunk base 0/4/8/12
    const int br  = t >> 1;            // B row 0..255
    const int bc0 = (t & 1) << 3;      // B chunk base 0/8

    const int NCHUNK = D_MODEL / 128;  // 16

    auto issue_chunk = [&](int c) {
        uint32_t abuf = sb + (uint32_t)(c & 1) * GSTAGE_BYTES;
        uint32_t bbuf = abuf + 32768u;
        const __half* Ag = Arow + (c << 7);
        const __half* Bg = Brow + (c << 7);
#pragma unroll
        for (int i = 0; i < 4; i++) {
            int cc = ac0 + i;
            cp_async16(abuf + (ar << 8) + ((uint32_t)(cc ^ (ar & 7)) << 4),
                       Ag + (size_t)ar * D_MODEL + (cc << 3));
        }
#pragma unroll
        for (int i = 0; i < 8; i++) {
            int cc = bc0 + i;
            cp_async16(bbuf + (br << 8) + ((uint32_t)(cc ^ (br & 7)) << 4),
                       Bg + (size_t)br * D_MODEL + (cc << 3));
        }
    };

    issue_chunk(0);
    CP_COMMIT();

#pragma unroll 1
    for (int c = 0; c < NCHUNK; c++) {
        CP_WAIT(0);
        __syncthreads();   // chunk c landed; all warps done with chunk c-1

        if (c + 1 < NCHUNK) issue_chunk(c + 1);
        CP_COMMIT();

        uint32_t ab = sb + (uint32_t)(c & 1) * GSTAGE_BYTES;
        uint32_t bb = ab + 32768u;

#pragma unroll
        for (int s = 0; s < 8; s++) {
            uint32_t af[2][4], bf[4][4];
#pragma unroll
            for (int mt = 0; mt < 2; mt++) {
                uint32_t addr = ab + ((arow + mt * 16) << 8)
                                   + (((2u * s + acsel) ^ asw7) << 4);
                LDSM_X4(af[mt][0], af[mt][1], af[mt][2], af[mt][3], addr);
            }
#pragma unroll
            for (int p = 0; p < 4; p++) {
                uint32_t addr = bb + ((brow + p * 16) << 8)
                                   + (((2u * s + bcsel) ^ bsw7) << 4);
                LDSM_X4(bf[p][0], bf[p][1], bf[p][2], bf[p][3], addr);
            }
#pragma unroll
            for (int mt = 0; mt < 2; mt++)
#pragma unroll
                for (int nt = 0; nt < 8; nt++)
                    mma_f16(acc[mt][nt], af[mt],
                            bf[nt >> 1][(nt & 1) * 2],
                            bf[nt >> 1][(nt & 1) * 2 + 1]);
        }
    }

    // ---- epilogue ----
    if (Cf != nullptr) {
#pragma unroll
        for (int mt = 0; mt < 2; mt++) {
            int re = row0 + wm + mt * 16 + (lane >> 2);
#pragma unroll
            for (int nt = 0; nt < 8; nt++) {
                int ce = col0 + wn + nt * 8 + ((lane & 3) << 1);
                *(float2*)(Cf + (size_t)re * D_MODEL + ce) =
                    make_float2(acc[mt][nt][0], acc[mt][nt][1]);
                *(float2*)(Cf + (size_t)(re + 8) * D_MODEL + ce) =
                    make_float2(acc[mt][nt][2], acc[mt][nt][3]);
            }
        }
    } else if (dovt) {
#pragma unroll
        for (int mt = 0; mt < 2; mt++) {
            int re = row0 + wm + mt * 16 + (lane >> 2);
#pragma unroll
            for (int nt = 0; nt < 8; nt++) {
                int ce = col0 + wn + nt * 8 + ((lane & 3) << 1);
                C[(size_t)ce * SEQ + re]           = __float2half_rn(acc[mt][nt][0]);
                C[(size_t)(ce + 1) * SEQ + re]     = __float2half_rn(acc[mt][nt][1]);
                C[(size_t)ce * SEQ + re + 8]       = __float2half_rn(acc[mt][nt][2]);
                C[(size_t)(ce + 1) * SEQ + re + 8] = __float2half_rn(acc[mt][nt][3]);
            }
        }
    } else {
#pragma unroll
        for (int mt = 0; mt < 2; mt++) {
            int re = row0 + wm + mt * 16 + (lane >> 2);
#pragma unroll
            for (int nt = 0; nt < 8; nt++) {
                int ce = col0 + wn + nt * 8 + ((lane & 3) << 1);
                float2 v0 = make_float2(acc[mt][nt][0], acc[mt][nt][1]);
                float2 v1 = make_float2(acc[mt][nt][2], acc[mt][nt][3]);
                if (dorope) {
                    int pidx = (ce & 127) >> 1;
                    float c0 = fc[(size_t)re * 64 + pidx];
                    float s0 = fs[(size_t)re * 64 + pidx];
                    float c1 = fc[(size_t)(re + 8) * 64 + pidx];
                    float s1 = fs[(size_t)(re + 8) * 64 + pidx];
                    v0 = make_float2(v0.x * c0 - v0.y * s0, v0.x * s0 + v0.y * c0);
                    v1 = make_float2(v1.x * c1 - v1.y * s1, v1.x * s1 + v1.y * c1);
                }
                *(uint32_t*)(C + (size_t)re * D_MODEL + ce)       = pack_half2(v0.x, v0.y);
                *(uint32_t*)(C + (size_t)(re + 8) * D_MODEL + ce) = pack_half2(v1.x, v1.y);
            }
        }
    }
}

// ---------------------------------------------------------------------------
// FlashAttention-2 fp16 v5 (R15-proven): register P reuse + log2-domain
// softmax (ex2.approx.f16x2) + row-sums via ones-column MMA.
// 256 threads / 8 warps, 128-row Q tile, 128-key KV tiles, 2-slot ring.
// ---------------------------------------------------------------------------
#define ATT_SMEM_BYTES (160 * 1024)

__global__ __launch_bounds__(256, 1) void attn_tc_kernel(
    const __half* __restrict__ Q, const __half* __restrict__ K,
    const __half* __restrict__ Vt, __half* __restrict__ O)
{
    extern __shared__ char smc[];
    uint32_t sb = smem_u32(smc);
    const uint32_t KBASE = sb + 32768u;
    const uint32_t VBASE = sb + 98304u;

    int t    = threadIdx.x;
    int lane = t & 31;
    int w    = t >> 5;
    int qt   = (int)gridDim.x - 1 - (int)blockIdx.x;
    int h    = blockIdx.y;
    int q0   = qt << 7;

    uint32_t arow  = (uint32_t)(lane & 15);
    uint32_t acsel = (uint32_t)((lane >> 4) & 1);
    uint32_t brow  = (uint32_t)((lane & 7) + ((lane >> 4) & 1) * 8);
    uint32_t bcsel = (uint32_t)((lane >> 3) & 1);
    uint32_t bsw   = brow & 7;

    const __half* Kh  = K  + h * HEAD_DIM;
    const __half* Vth = Vt + (size_t)(h * HEAD_DIM) * SEQ;

    auto issue_tile = [&](int kt) {
        uint32_t slot = (uint32_t)(kt & 1);
        const __half* Kg  = Kh  + ((size_t)kt << 7) * D_MODEL;
        const __half* Vtg = Vth + ((size_t)kt << 7);
#pragma unroll
        for (int i = 0; i < 8; i++) {
            int lin = t + (i << 8);
            int r   = lin >> 4;
            int c   = lin & 15;
            cp_async16(KBASE + slot * 32768u + (r << 8) + ((uint32_t)(c ^ (r & 7)) << 4),
                       Kg + (size_t)r * D_MODEL + (c << 3));
        }
#pragma unroll
        for (int i = 0; i < 8; i++) {
            int lin = t + (i << 8);
            int r   = lin >> 4;
            int c   = lin & 15;
            cp_async16(VBASE + slot * 32768u + (r << 8) + ((uint32_t)(c ^ (r & 7)) << 4),
                       Vtg + (size_t)r * SEQ + (c << 3));
        }
    };

    {
        const __half* Qg = Q + (size_t)q0 * D_MODEL + h * HEAD_DIM;
#pragma unroll
        for (int i = 0; i < 8; i++) {
            int lin = t + (i << 8);
            int r   = lin >> 4;
            int c   = lin & 15;
            cp_async16(sb + (r << 8) + ((uint32_t)(c ^ (r & 7)) << 4),
                       Qg + (size_t)r * D_MODEL + (c << 3));
        }
        CP_COMMIT();
    }
    issue_tile(0);
    CP_COMMIT();
    CP_WAIT(0);
    __syncthreads();

    uint32_t qf[8][4];
    {
        uint32_t qrow = arow + (uint32_t)(w << 4);
        uint32_t qsw  = qrow & 7;
#pragma unroll
        for (int s = 0; s < 8; s++) {
            uint32_t addr = sb + (qrow << 8) + (((2u * s + acsel) ^ qsw) << 4);
            LDSM_X4(qf[s][0], qf[s][1], qf[s][2], qf[s][3], addr);
        }
    }

    float oacc[16][4];
#pragma unroll
    for (int i = 0; i < 16; i++)
#pragma unroll
        for (int j = 0; j < 4; j++) oacc[i][j] = 0.0f;
    float mrow[2] = {-1e30f, -1e30f};
    float lrow[2] = {0.0f, 0.0f};

    const float scale2 = 0.08838834764831845f * 1.44269504088896340f;
    const uint32_t ONES = 0x3C003C00u;

#pragma unroll 1
    for (int kt = 0; kt <= qt; kt++) {
        if (kt > 0) {
            CP_WAIT(0);
            __syncthreads();
        }
        if (kt + 1 <= qt) {
            issue_tile(kt + 1);
            CP_COMMIT();
        }

        uint32_t slot = (uint32_t)(kt & 1);
        uint32_t kb = KBASE + slot * 32768u;
        uint32_t vb = VBASE + slot * 32768u;

        float sacc[16][4];
#pragma unroll
        for (int nt = 0; nt < 16; nt++)
#pragma unroll
            for (int e = 0; e < 4; e++) sacc[nt][e] = 0.0f;

#pragma unroll
        for (int s = 0; s < 8; s++) {
            uint32_t bf[8][4];
#pragma unroll
            for (int p = 0; p < 8; p++) {
                uint32_t addr = kb + ((brow + (uint32_t)(p << 4)) << 8)
                                   + (((2u * s + bcsel) ^ bsw) << 4);
                LDSM_X4(bf[p][0], bf[p][1], bf[p][2], bf[p][3], addr);
            }
#pragma unroll
            for (int nt = 0; nt < 16; nt++)
                mma_f16(sacc[nt], qf[s],
                        bf[nt >> 1][(nt & 1) * 2],
                        bf[nt >> 1][(nt & 1) * 2 + 1]);
        }

        bool need_mask = (kt == qt);
        int grow = q0 + (w << 4) + (lane >> 2);
#pragma unroll
        for (int nt = 0; nt < 16; nt++) {
#pragma unroll
            for (int e = 0; e < 4; e++) {
                float v = sacc[nt][e] * scale2;
                if (need_mask) {
                    int row = grow + (e >> 1) * 8;
                    int col = (kt << 7) + (nt << 3) + ((lane & 3) << 1) + (e & 1);
                    if (col > row) v = -30000.0f;
                }
                sacc[nt][e] = v;
            }
        }

        float alpha[2];
#pragma unroll
        for (int half = 0; half < 2; half++) {
            float mx = -1e30f;
#pragma unroll
            for (int nt = 0; nt < 16; nt++)
                mx = fmaxf(mx, fmaxf(sacc[nt][2 * half], sacc[nt][2 * half + 1]));
            mx = fmaxf(mx, __shfl_xor_sync(0xffffffffu, mx, 1));
            mx = fmaxf(mx, __shfl_xor_sync(0xffffffffu, mx, 2));
            float mnew = fmaxf(mrow[half], mx);
            alpha[half] = ex2_f32(mrow[half] - mnew);
#pragma unroll
            for (int nt = 0; nt < 16; nt++) {
                sacc[nt][2 * half]     -= mnew;
                sacc[nt][2 * half + 1] -= mnew;
            }
            mrow[half] = mnew;
        }
#pragma unroll
        for (int nt = 0; nt < 16; nt++) {
            oacc[nt][0] *= alpha[0];  oacc[nt][1] *= alpha[0];
            oacc[nt][2] *= alpha[1];  oacc[nt][3] *= alpha[1];
        }

        float lacc[4] = {0.0f, 0.0f, 0.0f, 0.0f};
#pragma unroll
        for (int s = 0; s < 8; s++) {
            uint32_t pf[4];
            pf[0] = ex2_f16x2(pack_half2(sacc[2 * s][0],     sacc[2 * s][1]));
            pf[1] = ex2_f16x2(pack_half2(sacc[2 * s][2],     sacc[2 * s][3]));
            pf[2] = ex2_f16x2(pack_half2(sacc[2 * s + 1][0], sacc[2 * s + 1][1]));
            pf[3] = ex2_f16x2(pack_half2(sacc[2 * s + 1][2], sacc[2 * s + 1][3]));
            mma_f16(lacc, pf, ONES, ONES);
#pragma unroll
            for (int p = 0; p < 8; p++) {
                uint32_t bvf[4];
                uint32_t addrB = vb + ((brow + (uint32_t)(p << 4)) << 8)
                                    + (((2u * s + bcsel) ^ bsw) << 4);
                LDSM_X4(bvf[0], bvf[1], bvf[2], bvf[3], addrB);
                mma_f16(oacc[2 * p],     pf, bvf[0], bvf[1]);
                mma_f16(oacc[2 * p + 1], pf, bvf[2], bvf[3]);
            }
        }
        lrow[0] = lrow[0] * alpha[0] + lacc[0];
        lrow[1] = lrow[1] * alpha[1] + lacc[2];
    }

    float inv0 = 1.0f / lrow[0];
    float inv1 = 1.0f / lrow[1];
    int row = q0 + (w << 4) + (lane >> 2);
#pragma unroll
    for (int nt = 0; nt < 16; nt++) {
        int col = h * HEAD_DIM + (nt << 3) + ((lane & 3) << 1);
        *(uint32_t*)(O + (size_t)row * D_MODEL + col) =
            pack_half2(oacc[nt][0] * inv0, oacc[nt][1] * inv0);
        *(uint32_t*)(O + (size_t)(row + 8) * D_MODEL + col) =
            pack_half2(oacc[nt][2] * inv1, oacc[nt][3] * inv1);
    }
}

// ---------------------------------------------------------------------------
extern "C" void kernel_launch(void* const* d_in, const int* in_sizes, int n_in,
                              void* d_out, int out_size)
{
    (void)in_sizes; (void)n_in; (void)out_size;
    const float* x  = (const float*)d_in[0];
    const float* fc = (const float*)d_in[1];
    const float* fs = (const float*)d_in[2];
    const float* wq = (const float*)d_in[4];
    const float* wk = (const float*)d_in[5];
    const float* wv = (const float*)d_in[6];
    const float* wo = (const float*)d_in[7];
    float* out = (float*)d_out;

    __half *Qp, *Kp, *Vtp, *Ap, *Xp, *WT4p;
    cudaGetSymbolAddress((void**)&Qp,   g_Q);
    cudaGetSymbolAddress((void**)&Kp,   g_K);
    cudaGetSymbolAddress((void**)&Vtp,  g_Vt);
    cudaGetSymbolAddress((void**)&Ap,   g_A);
    cudaGetSymbolAddress((void**)&Xp,   g_X);
    cudaGetSymbolAddress((void**)&WT4p, g_WT4);

    cudaFuncSetAttribute(gemm_tc_kernel, cudaFuncAttributeMaxDynamicSharedMemorySize,
                         GEMM_SMEM_BYTES);
    cudaFuncSetAttribute(attn_tc_kernel, cudaFuncAttributeMaxDynamicSharedMemorySize,
                         ATT_SMEM_BYTES);

    const size_t WSZ = (size_t)D_MODEL * D_MODEL;

    prep_kernel<<<dim3(64, 64, 5), dim3(32, 8)>>>(x, wq, wk, wv, wo, Xp, WT4p);

    gemm_tc_kernel<<<dim3(24, 16), 512, GEMM_SMEM_BYTES>>>(
        Xp, WT4p, Qp, Kp, Vtp, nullptr, fc, fs, 8, 2, 2);

    attn_tc_kernel<<<dim3(SEQ / 128, N_HEADS), 256, ATT_SMEM_BYTES>>>(Qp, Kp, Vtp, Ap);

    gemm_tc_kernel<<<dim3(8, 16), 512, GEMM_SMEM_BYTES>>>(
        Ap, WT4p + 3 * WSZ, nullptr, nullptr, nullptr, out, fc, fs, 8, 0, -1);
}

// round 17
// speedup vs baseline: 1.4715x; 1.4715x over previous
#include <cuda_runtime.h>
#include <cuda_fp16.h>
#include <cstdint>
#include <math.h>

#define D_MODEL 2048
#define SEQ     2048
#define N_HEADS 16
#define HEAD_DIM 128

__device__ __half g_Q[SEQ * D_MODEL];
__device__ __half g_K[SEQ * D_MODEL];
__device__ __half g_Vt[D_MODEL * SEQ];
__device__ __half g_A[SEQ * D_MODEL];
__device__ __half g_X[SEQ * D_MODEL];
__device__ __half g_WT4[4 * D_MODEL * D_MODEL];

// ---------------------------------------------------------------------------
static __device__ __forceinline__ uint32_t smem_u32(const void* p) {
    return (uint32_t)__cvta_generic_to_shared(p);
}

#define LDSM_X4(r0, r1, r2, r3, addr) \
    asm volatile("ldmatrix.sync.aligned.m8n8.x4.shared.b16 {%0,%1,%2,%3}, [%4];" \
                 : "=r"(r0), "=r"(r1), "=r"(r2), "=r"(r3) : "r"(addr))

static __device__ __forceinline__ void mma_f16(
    float* c, const uint32_t* a, uint32_t b0, uint32_t b1)
{
    asm volatile(
        "mma.sync.aligned.m16n8k16.row.col.f32.f16.f16.f32 "
        "{%0,%1,%2,%3}, {%4,%5,%6,%7}, {%8,%9}, {%0,%1,%2,%3};"
        : "+f"(c[0]), "+f"(c[1]), "+f"(c[2]), "+f"(c[3])
        : "r"(a[0]), "r"(a[1]), "r"(a[2]), "r"(a[3]), "r"(b0), "r"(b1));
}

static __device__ __forceinline__ uint32_t pack_half2(float lo, float hi) {
    uint32_t r;
    asm("cvt.rn.f16x2.f32 %0, %1, %2;" : "=r"(r) : "f"(hi), "f"(lo));
    return r;
}

static __device__ __forceinline__ uint32_t ex2_f16x2(uint32_t a) {
    uint32_t r;
    asm("ex2.approx.f16x2 %0, %1;" : "=r"(r) : "r"(a));
    return r;
}

static __device__ __forceinline__ float ex2_f32(float x) {
    float r;
    asm("ex2.approx.f32 %0, %1;" : "=f"(r) : "f"(x));
    return r;
}

static __device__ __forceinline__ void cp_async16(uint32_t dst, const void* src) {
    asm volatile("cp.async.cg.shared.global [%0], [%1], 16;"
                 :: "r"(dst), "l"(src) : "memory");
}
#define CP_COMMIT() asm volatile("cp.async.commit_group;" ::: "memory")
#define CP_WAIT(n)  asm volatile("cp.async.wait_group %0;" :: "n"(n) : "memory")

// ---------------------------------------------------------------------------
// prep: z=0 convert x->fp16 ; z=1..4 transpose+convert wq/wk/wv/wo
// ---------------------------------------------------------------------------
__global__ __launch_bounds__(256) void prep_kernel(
    const float* __restrict__ x,
    const float* __restrict__ wq, const float* __restrict__ wk,
    const float* __restrict__ wv, const float* __restrict__ wo,
    __half* __restrict__ X, __half* __restrict__ WT)
{
    const size_t WSZ = (size_t)D_MODEL * D_MODEL;
    int z = blockIdx.z;
    if (z == 0) {
        int c = blockIdx.x * 32 + threadIdx.x;
#pragma unroll
        for (int i = 0; i < 4; i++) {
            int r = blockIdx.y * 32 + threadIdx.y + i * 8;
            X[(size_t)r * D_MODEL + c] = __float2half_rn(x[(size_t)r * D_MODEL + c]);
        }
        return;
    }
    const float* in = (z == 1) ? wq : (z == 2) ? wk : (z == 3) ? wv : wo;
    __half* out = WT + (size_t)(z - 1) * WSZ;

    __shared__ float tile[32][33];
    int xx = blockIdx.x * 32 + threadIdx.x;
    int yy = blockIdx.y * 32 + threadIdx.y;
#pragma unroll
    for (int i = 0; i < 32; i += 8)
        tile[threadIdx.y + i][threadIdx.x] = in[(size_t)(yy + i) * D_MODEL + xx];
    __syncthreads();
    xx = blockIdx.y * 32 + threadIdx.x;
    yy = blockIdx.x * 32 + threadIdx.y;
#pragma unroll
    for (int i = 0; i < 32; i += 8)
        out[(size_t)(yy + i) * D_MODEL + xx] = __float2half_rn(tile[threadIdx.x][threadIdx.y + i]);
}

// ---------------------------------------------------------------------------
// fp16 mma.sync GEMM v4: CTA 128x128, 256 threads / 8 warps (4x2),
// warp 32x64, BK=64, 3-stage cp.async (32KB/stage = 96KB), 2 CTAs/SM.
// ---------------------------------------------------------------------------
#define GSTAGE_BYTES 32768
#define GEMM_SMEM_BYTES (3 * GSTAGE_BYTES)

__global__ __launch_bounds__(256, 2) void gemm_tc_kernel(
    const __half* __restrict__ A, const __half* __restrict__ BT,
    __half* __restrict__ C0, __half* __restrict__ C1, __half* __restrict__ C2,
    float* __restrict__ Cf,
    const float* __restrict__ fc, const float* __restrict__ fs,
    int tiles_per_mat, int rope_mats, int vt_mat)
{
    extern __shared__ char smc[];
    uint32_t sb = smem_u32(smc);

    int t    = threadIdx.x;
    int lane = t & 31;
    int wid  = t >> 5;
    int row0 = blockIdx.y << 7;
    int bx   = blockIdx.x;
    int mat  = bx / tiles_per_mat;
    int col0 = (bx % tiles_per_mat) << 7;
    __half* C = (mat == 0) ? C0 : (mat == 1 ? C1 : C2);
    const __half* Arow = A + (size_t)row0 * D_MODEL;
    const __half* Brow = BT + ((size_t)bx << 7) * D_MODEL;
    bool dorope = (mat < rope_mats);
    bool dovt   = (mat == vt_mat);

    int wm = (wid >> 1) << 5;    // 0/32/64/96
    int wn = (wid & 1) << 6;     // 0/64

    float acc[2][8][4];
#pragma unroll
    for (int i = 0; i < 2; i++)
#pragma unroll
        for (int j = 0; j < 8; j++)
#pragma unroll
            for (int q = 0; q < 4; q++) acc[i][j][q] = 0.0f;

    uint32_t arow  = (uint32_t)(wm + (lane & 15));
    uint32_t acsel = (uint32_t)((lane >> 4) & 1);
    uint32_t brow  = (uint32_t)(wn + (lane & 7) + ((lane >> 4) & 1) * 8);
    uint32_t bcsel = (uint32_t)((lane >> 3) & 1);
    uint32_t asw7  = arow & 7;
    uint32_t bsw7  = brow & 7;

    // copy geometry: 256 threads; tile 128 rows x 8 chunks (128B rows)
    const int crr = t >> 3;   // 0..31
    const int ccc = t & 7;

    const int NCHUNK = D_MODEL / 64;   // 32

    auto issue_chunk = [&](int c) {
        uint32_t abuf = sb + (uint32_t)(c % 3) * GSTAGE_BYTES;
        uint32_t bbuf = abuf + 16384u;
        const __half* Ag = Arow + (c << 6);
        const __half* Bg = Brow + (c << 6);
#pragma unroll
        for (int i = 0; i < 4; i++) {
            int r = crr + (i << 5);
            cp_async16(abuf + (r << 7) + ((uint32_t)(ccc ^ (r & 7)) << 4),
                       Ag + (size_t)r * D_MODEL + (ccc << 3));
        }
#pragma unroll
        for (int i = 0; i < 4; i++) {
            int r = crr + (i << 5);
            cp_async16(bbuf + (r << 7) + ((uint32_t)(ccc ^ (r & 7)) << 4),
                       Bg + (size_t)r * D_MODEL + (ccc << 3));
        }
    };

    issue_chunk(0); CP_COMMIT();
    issue_chunk(1); CP_COMMIT();

#pragma unroll 1
    for (int c = 0; c < NCHUNK; c++) {
        CP_WAIT(1);
        __syncthreads();   // chunk c landed; all warps done with chunk c-1

        if (c + 2 < NCHUNK) issue_chunk(c + 2);
        CP_COMMIT();

        uint32_t ab = sb + (uint32_t)(c % 3) * GSTAGE_BYTES;
        uint32_t bb = ab + 16384u;

#pragma unroll
        for (int s = 0; s < 4; s++) {
            uint32_t af[2][4], bf[4][4];
#pragma unroll
            for (int mt = 0; mt < 2; mt++) {
                uint32_t addr = ab + ((arow + mt * 16) << 7)
                                   + (((2u * s + acsel) ^ asw7) << 4);
                LDSM_X4(af[mt][0], af[mt][1], af[mt][2], af[mt][3], addr);
            }
#pragma unroll
            for (int p = 0; p < 4; p++) {
                uint32_t addr = bb + ((brow + p * 16) << 7)
                                   + (((2u * s + bcsel) ^ bsw7) << 4);
                LDSM_X4(bf[p][0], bf[p][1], bf[p][2], bf[p][3], addr);
            }
#pragma unroll
            for (int mt = 0; mt < 2; mt++)
#pragma unroll
                for (int nt = 0; nt < 8; nt++)
                    mma_f16(acc[mt][nt], af[mt],
                            bf[nt >> 1][(nt & 1) * 2],
                            bf[nt >> 1][(nt & 1) * 2 + 1]);
        }
    }

    // ---- epilogue ----
    if (Cf != nullptr) {
#pragma unroll
        for (int mt = 0; mt < 2; mt++) {
            int re = row0 + wm + mt * 16 + (lane >> 2);
#pragma unroll
            for (int nt = 0; nt < 8; nt++) {
                int ce = col0 + wn + nt * 8 + ((lane & 3) << 1);
                *(float2*)(Cf + (size_t)re * D_MODEL + ce) =
                    make_float2(acc[mt][nt][0], acc[mt][nt][1]);
                *(float2*)(Cf + (size_t)(re + 8) * D_MODEL + ce) =
                    make_float2(acc[mt][nt][2], acc[mt][nt][3]);
            }
        }
    } else if (dovt) {
#pragma unroll
        for (int mt = 0; mt < 2; mt++) {
            int re = row0 + wm + mt * 16 + (lane >> 2);
#pragma unroll
            for (int nt = 0; nt < 8; nt++) {
                int ce = col0 + wn + nt * 8 + ((lane & 3) << 1);
                C[(size_t)ce * SEQ + re]           = __float2half_rn(acc[mt][nt][0]);
                C[(size_t)(ce + 1) * SEQ + re]     = __float2half_rn(acc[mt][nt][1]);
                C[(size_t)ce * SEQ + re + 8]       = __float2half_rn(acc[mt][nt][2]);
                C[(size_t)(ce + 1) * SEQ + re + 8] = __float2half_rn(acc[mt][nt][3]);
            }
        }
    } else {
#pragma unroll
        for (int mt = 0; mt < 2; mt++) {
            int re = row0 + wm + mt * 16 + (lane >> 2);
#pragma unroll
            for (int nt = 0; nt < 8; nt++) {
                int ce = col0 + wn + nt * 8 + ((lane & 3) << 1);
                float2 v0 = make_float2(acc[mt][nt][0], acc[mt][nt][1]);
                float2 v1 = make_float2(acc[mt][nt][2], acc[mt][nt][3]);
                if (dorope) {
                    int pidx = (ce & 127) >> 1;
                    float c0 = fc[(size_t)re * 64 + pidx];
                    float s0 = fs[(size_t)re * 64 + pidx];
                    float c1 = fc[(size_t)(re + 8) * 64 + pidx];
                    float s1 = fs[(size_t)(re + 8) * 64 + pidx];
                    v0 = make_float2(v0.x * c0 - v0.y * s0, v0.x * s0 + v0.y * c0);
                    v1 = make_float2(v1.x * c1 - v1.y * s1, v1.x * s1 + v1.y * c1);
                }
                *(uint32_t*)(C + (size_t)re * D_MODEL + ce)       = pack_half2(v0.x, v0.y);
                *(uint32_t*)(C + (size_t)(re + 8) * D_MODEL + ce) = pack_half2(v1.x, v1.y);
            }
        }
    }
}

// ---------------------------------------------------------------------------
// FlashAttention-2 fp16 v5 (R15-proven): register P reuse + log2-domain
// softmax (ex2.approx.f16x2) + row-sums via ones-column MMA.
// 256 threads / 8 warps, 128-row Q tile, 128-key KV tiles, 2-slot ring.
// ---------------------------------------------------------------------------
#define ATT_SMEM_BYTES (160 * 1024)

__global__ __launch_bounds__(256, 1) void attn_tc_kernel(
    const __half* __restrict__ Q, const __half* __restrict__ K,
    const __half* __restrict__ Vt, __half* __restrict__ O)
{
    extern __shared__ char smc[];
    uint32_t sb = smem_u32(smc);
    const uint32_t KBASE = sb + 32768u;
    const uint32_t VBASE = sb + 98304u;

    int t    = threadIdx.x;
    int lane = t & 31;
    int w    = t >> 5;
    int qt   = (int)gridDim.x - 1 - (int)blockIdx.x;
    int h    = blockIdx.y;
    int q0   = qt << 7;

    uint32_t arow  = (uint32_t)(lane & 15);
    uint32_t acsel = (uint32_t)((lane >> 4) & 1);
    uint32_t brow  = (uint32_t)((lane & 7) + ((lane >> 4) & 1) * 8);
    uint32_t bcsel = (uint32_t)((lane >> 3) & 1);
    uint32_t bsw   = brow & 7;

    const __half* Kh  = K  + h * HEAD_DIM;
    const __half* Vth = Vt + (size_t)(h * HEAD_DIM) * SEQ;

    auto issue_tile = [&](int kt) {
        uint32_t slot = (uint32_t)(kt & 1);
        const __half* Kg  = Kh  + ((size_t)kt << 7) * D_MODEL;
        const __half* Vtg = Vth + ((size_t)kt << 7);
#pragma unroll
        for (int i = 0; i < 8; i++) {
            int lin = t + (i << 8);
            int r   = lin >> 4;
            int c   = lin & 15;
            cp_async16(KBASE + slot * 32768u + (r << 8) + ((uint32_t)(c ^ (r & 7)) << 4),
                       Kg + (size_t)r * D_MODEL + (c << 3));
        }
#pragma unroll
        for (int i = 0; i < 8; i++) {
            int lin = t + (i << 8);
            int r   = lin >> 4;
            int c   = lin & 15;
            cp_async16(VBASE + slot * 32768u + (r << 8) + ((uint32_t)(c ^ (r & 7)) << 4),
                       Vtg + (size_t)r * SEQ + (c << 3));
        }
    };

    {
        const __half* Qg = Q + (size_t)q0 * D_MODEL + h * HEAD_DIM;
#pragma unroll
        for (int i = 0; i < 8; i++) {
            int lin = t + (i << 8);
            int r   = lin >> 4;
            int c   = lin & 15;
            cp_async16(sb + (r << 8) + ((uint32_t)(c ^ (r & 7)) << 4),
                       Qg + (size_t)r * D_MODEL + (c << 3));
        }
        CP_COMMIT();
    }
    issue_tile(0);
    CP_COMMIT();
    CP_WAIT(0);
    __syncthreads();

    uint32_t qf[8][4];
    {
        uint32_t qrow = arow + (uint32_t)(w << 4);
        uint32_t qsw  = qrow & 7;
#pragma unroll
        for (int s = 0; s < 8; s++) {
            uint32_t addr = sb + (qrow << 8) + (((2u * s + acsel) ^ qsw) << 4);
            LDSM_X4(qf[s][0], qf[s][1], qf[s][2], qf[s][3], addr);
        }
    }

    float oacc[16][4];
#pragma unroll
    for (int i = 0; i < 16; i++)
#pragma unroll
        for (int j = 0; j < 4; j++) oacc[i][j] = 0.0f;
    float mrow[2] = {-1e30f, -1e30f};
    float lrow[2] = {0.0f, 0.0f};

    const float scale2 = 0.08838834764831845f * 1.44269504088896340f;
    const uint32_t ONES = 0x3C003C00u;

#pragma unroll 1
    for (int kt = 0; kt <= qt; kt++) {
        if (kt > 0) {
            CP_WAIT(0);
            __syncthreads();
        }
        if (kt + 1 <= qt) {
            issue_tile(kt + 1);
            CP_COMMIT();
        }

        uint32_t slot = (uint32_t)(kt & 1);
        uint32_t kb = KBASE + slot * 32768u;
        uint32_t vb = VBASE + slot * 32768u;

        float sacc[16][4];
#pragma unroll
        for (int nt = 0; nt < 16; nt++)
#pragma unroll
            for (int e = 0; e < 4; e++) sacc[nt][e] = 0.0f;

#pragma unroll
        for (int s = 0; s < 8; s++) {
            uint32_t bf[8][4];
#pragma unroll
            for (int p = 0; p < 8; p++) {
                uint32_t addr = kb + ((brow + (uint32_t)(p << 4)) << 8)
                                   + (((2u * s + bcsel) ^ bsw) << 4);
                LDSM_X4(bf[p][0], bf[p][1], bf[p][2], bf[p][3], addr);
            }
#pragma unroll
            for (int nt = 0; nt < 16; nt++)
                mma_f16(sacc[nt], qf[s],
                        bf[nt >> 1][(nt & 1) * 2],
                        bf[nt >> 1][(nt & 1) * 2 + 1]);
        }

        bool need_mask = (kt == qt);
        int grow = q0 + (w << 4) + (lane >> 2);
#pragma unroll
        for (int nt = 0; nt < 16; nt++) {
#pragma unroll
            for (int e = 0; e < 4; e++) {
                float v = sacc[nt][e] * scale2;
                if (need_mask) {
                    int row = grow + (e >> 1) * 8;
                    int col = (kt << 7) + (nt << 3) + ((lane & 3) << 1) + (e & 1);
                    if (col > row) v = -30000.0f;
                }
                sacc[nt][e] = v;
            }
        }

        float alpha[2];
#pragma unroll
        for (int half = 0; half < 2; half++) {
            float mx = -1e30f;
#pragma unroll
            for (int nt = 0; nt < 16; nt++)
                mx = fmaxf(mx, fmaxf(sacc[nt][2 * half], sacc[nt][2 * half + 1]));
            mx = fmaxf(mx, __shfl_xor_sync(0xffffffffu, mx, 1));
            mx = fmaxf(mx, __shfl_xor_sync(0xffffffffu, mx, 2));
            float mnew = fmaxf(mrow[half], mx);
            alpha[half] = ex2_f32(mrow[half] - mnew);
#pragma unroll
            for (int nt = 0; nt < 16; nt++) {
                sacc[nt][2 * half]     -= mnew;
                sacc[nt][2 * half + 1] -= mnew;
            }
            mrow[half] = mnew;
        }
#pragma unroll
        for (int nt = 0; nt < 16; nt++) {
            oacc[nt][0] *= alpha[0];  oacc[nt][1] *= alpha[0];
            oacc[nt][2] *= alpha[1];  oacc[nt][3] *= alpha[1];
        }

        float lacc[4] = {0.0f, 0.0f, 0.0f, 0.0f};
#pragma unroll
        for (int s = 0; s < 8; s++) {
            uint32_t pf[4];
            pf[0] = ex2_f16x2(pack_half2(sacc[2 * s][0],     sacc[2 * s][1]));
            pf[1] = ex2_f16x2(pack_half2(sacc[2 * s][2],     sacc[2 * s][3]));
            pf[2] = ex2_f16x2(pack_half2(sacc[2 * s + 1][0], sacc[2 * s + 1][1]));
            pf[3] = ex2_f16x2(pack_half2(sacc[2 * s + 1][2], sacc[2 * s + 1][3]));
            mma_f16(lacc, pf, ONES, ONES);
#pragma unroll
            for (int p = 0; p < 8; p++) {
                uint32_t bvf[4];
                uint32_t addrB = vb + ((brow + (uint32_t)(p << 4)) << 8)
                                    + (((2u * s + bcsel) ^ bsw) << 4);
                LDSM_X4(bvf[0], bvf[1], bvf[2], bvf[3], addrB);
                mma_f16(oacc[2 * p],     pf, bvf[0], bvf[1]);
                mma_f16(oacc[2 * p + 1], pf, bvf[2], bvf[3]);
            }
        }
        lrow[0] = lrow[0] * alpha[0] + lacc[0];
        lrow[1] = lrow[1] * alpha[1] + lacc[2];
    }

    float inv0 = 1.0f / lrow[0];
    float inv1 = 1.0f / lrow[1];
    int row = q0 + (w << 4) + (lane >> 2);
#pragma unroll
    for (int nt = 0; nt < 16; nt++) {
        int col = h * HEAD_DIM + (nt << 3) + ((lane & 3) << 1);
        *(uint32_t*)(O + (size_t)row * D_MODEL + col) =
            pack_half2(oacc[nt][0] * inv0, oacc[nt][1] * inv0);
        *(uint32_t*)(O + (size_t)(row + 8) * D_MODEL + col) =
            pack_half2(oacc[nt][2] * inv1, oacc[nt][3] * inv1);
    }
}

// ---------------------------------------------------------------------------
extern "C" void kernel_launch(void* const* d_in, const int* in_sizes, int n_in,
                              void* d_out, int out_size)
{
    (void)in_sizes; (void)n_in; (void)out_size;
    const float* x  = (const float*)d_in[0];
    const float* fc = (const float*)d_in[1];
    const float* fs = (const float*)d_in[2];
    const float* wq = (const float*)d_in[4];
    const float* wk = (const float*)d_in[5];
    const float* wv = (const float*)d_in[6];
    const float* wo = (const float*)d_in[7];
    float* out = (float*)d_out;

    __half *Qp, *Kp, *Vtp, *Ap, *Xp, *WT4p;
    cudaGetSymbolAddress((void**)&Qp,   g_Q);
    cudaGetSymbolAddress((void**)&Kp,   g_K);
    cudaGetSymbolAddress((void**)&Vtp,  g_Vt);
    cudaGetSymbolAddress((void**)&Ap,   g_A);
    cudaGetSymbolAddress((void**)&Xp,   g_X);
    cudaGetSymbolAddress((void**)&WT4p, g_WT4);

    cudaFuncSetAttribute(gemm_tc_kernel, cudaFuncAttributeMaxDynamicSharedMemorySize,
                         GEMM_SMEM_BYTES);
    cudaFuncSetAttribute(attn_tc_kernel, cudaFuncAttributeMaxDynamicSharedMemorySize,
                         ATT_SMEM_BYTES);

    const size_t WSZ = (size_t)D_MODEL * D_MODEL;

    prep_kernel<<<dim3(64, 64, 5), dim3(32, 8)>>>(x, wq, wk, wv, wo, Xp, WT4p);

    // fused QKV: N = 6144 -> 48 x-tiles of 128; tiles_per_mat = 16
    gemm_tc_kernel<<<dim3(48, 16), 256, GEMM_SMEM_BYTES>>>(
        Xp, WT4p, Qp, Kp, Vtp, nullptr, fc, fs, 16, 2, 2);

    attn_tc_kernel<<<dim3(SEQ / 128, N_HEADS), 256, ATT_SMEM_BYTES>>>(Qp, Kp, Vtp, Ap);

    // proj: N = 2048 -> 16 x-tiles
    gemm_tc_kernel<<<dim3(16, 16), 256, GEMM_SMEM_BYTES>>>(
        Ap, WT4p + 3 * WSZ, nullptr, nullptr, nullptr, out, fc, fs, 16, 0, -1);
}